// round 1
// baseline (speedup 1.0000x reference)
#include <cuda_runtime.h>

// ShiftDecoderNet fused kernel: 3-layer MLP (LN+ReLU) + softmax + causal shift-sum.
// One CTA = 64 rows. 8 warps x 8 rows/warp. Each lane owns 8 output cols
// (j = 4*lane .. 4*lane+3 and 128+4*lane .. +3) x 8 rows of fp32 accumulators,
// packed as f32x2 for fma.rn.f32x2. Weights staged through a 128KB shared buffer.

#define BITS 64
#define HID 256
#define RB 64      // rows per block
#define NT 256     // threads per block
#define RW 8       // rows per warp

__device__ __forceinline__ void ffma2(unsigned long long &c, unsigned long long a, unsigned long long b) {
    asm("fma.rn.f32x2 %0, %1, %2, %0;" : "+l"(c) : "l"(a), "l"(b));
}
__device__ __forceinline__ unsigned long long dup2(float x) {
    unsigned long long d;
    asm("mov.b64 %0, {%1, %1};" : "=l"(d) : "f"(x));
    return d;
}
__device__ __forceinline__ float2 unpk(unsigned long long v) {
    float2 r;
    asm("mov.b64 {%0, %1}, %2;" : "=f"(r.x), "=f"(r.y) : "l"(v));
    return r;
}
__device__ __forceinline__ float wredsum(float v) {
    #pragma unroll
    for (int o = 16; o; o >>= 1) v += __shfl_xor_sync(0xffffffffu, v, o);
    return v;
}
__device__ __forceinline__ float wredmax(float v) {
    #pragma unroll
    for (int o = 16; o; o >>= 1) v = fmaxf(v, __shfl_xor_sync(0xffffffffu, v, o));
    return v;
}

// Shared layout (floats):
//   sBUF: [0, 32768)          128KB weight staging (W1T / W2 half / W3T)
//   sH:   [32768, 49152)      64 rows x 256 activations (h1, then h2, then probs)
//   sX:   [49152, 53248)      64 x 64 shift_bits
//   sA:   [53248, 57344)      64 x 64 a_bits
#define SMEM_FLOATS 57344

extern "C" __global__ void __launch_bounds__(NT, 1)
shiftdec_fused(const float* __restrict__ a_bits, const float* __restrict__ shift_bits,
               const float* __restrict__ W1, const float* __restrict__ b1,
               const float* __restrict__ g1, const float* __restrict__ be1,
               const float* __restrict__ W2, const float* __restrict__ b2,
               const float* __restrict__ g2, const float* __restrict__ be2,
               const float* __restrict__ W3, const float* __restrict__ b3,
               float* __restrict__ out)
{
    extern __shared__ float smem[];
    float* sBUF = smem;
    float* sH   = smem + 32768;
    float* sX   = smem + 49152;
    float* sA   = smem + 53248;

    const int tid = threadIdx.x;
    const int l   = tid & 31;
    const int w   = tid >> 5;
    const int wr  = w * RW;                 // local row base for this warp
    const int r0  = blockIdx.x * RB;        // global row base
    const int j0  = l * 4;

    // ---- cooperative loads: sX, sA (vectorized), W1T into sBUF ----
    {
        const float4* xs = (const float4*)(shift_bits + (size_t)r0 * BITS);
        const float4* as = (const float4*)(a_bits + (size_t)r0 * BITS);
        float4* dx = (float4*)sX;
        float4* da = (float4*)sA;
        #pragma unroll
        for (int it = 0; it < (RB * BITS / 4) / NT; ++it) {
            dx[tid + NT * it] = xs[tid + NT * it];
            da[tid + NT * it] = as[tid + NT * it];
        }
        // W1T: sBUF[k*256 + j] = W1[j*64 + k]; thread tid streams row j=tid.
        #pragma unroll
        for (int it = 0; it < 16; ++it) {
            float4 v = *(const float4*)(W1 + tid * 64 + 4 * it);
            sBUF[(4 * it + 0) * 256 + tid] = v.x;
            sBUF[(4 * it + 1) * 256 + tid] = v.y;
            sBUF[(4 * it + 2) * 256 + tid] = v.z;
            sBUF[(4 * it + 3) * 256 + tid] = v.w;
        }
    }
    __syncthreads();

    // ================= Stage 1: h1 = relu(LN(x @ W1^T + b1)) =================
    unsigned long long acc[RW][4];
    #pragma unroll
    for (int r = 0; r < RW; ++r)
        #pragma unroll
        for (int p = 0; p < 4; ++p) acc[r][p] = 0ull;

    for (int k = 0; k < 64; ++k) {
        const float* wrow = sBUF + (k << 8);
        ulonglong2 wa = *(const ulonglong2*)(wrow + j0);
        ulonglong2 wb = *(const ulonglong2*)(wrow + 128 + j0);
        #pragma unroll
        for (int r = 0; r < RW; ++r) {
            unsigned long long hd = dup2(sX[(wr + r) * 64 + k]);
            ffma2(acc[r][0], wa.x, hd);
            ffma2(acc[r][1], wa.y, hd);
            ffma2(acc[r][2], wb.x, hd);
            ffma2(acc[r][3], wb.y, hd);
        }
    }

    // LN1 + ReLU -> sH (own rows)
    {
        float bj[8], gj[8], bej[8];
        #pragma unroll
        for (int c = 0; c < 4; ++c) {
            bj[c]      = b1[j0 + c];        bj[4 + c]  = b1[128 + j0 + c];
            gj[c]      = g1[j0 + c];        gj[4 + c]  = g1[128 + j0 + c];
            bej[c]     = be1[j0 + c];       bej[4 + c] = be1[128 + j0 + c];
        }
        #pragma unroll
        for (int r = 0; r < RW; ++r) {
            float v[8]; float2 t;
            t = unpk(acc[r][0]); v[0] = t.x + bj[0]; v[1] = t.y + bj[1];
            t = unpk(acc[r][1]); v[2] = t.x + bj[2]; v[3] = t.y + bj[3];
            t = unpk(acc[r][2]); v[4] = t.x + bj[4]; v[5] = t.y + bj[5];
            t = unpk(acc[r][3]); v[6] = t.x + bj[6]; v[7] = t.y + bj[7];
            float s = 0.f, s2 = 0.f;
            #pragma unroll
            for (int c = 0; c < 8; ++c) { s += v[c]; s2 += v[c] * v[c]; }
            s = wredsum(s); s2 = wredsum(s2);
            float mean = s * (1.0f / 256.0f);
            float var  = s2 * (1.0f / 256.0f) - mean * mean;
            float rstd = rsqrtf(var + 1e-5f);
            float h[8];
            #pragma unroll
            for (int c = 0; c < 8; ++c)
                h[c] = fmaxf(0.f, (v[c] - mean) * rstd * gj[c] + bej[c]);
            float* hp = sH + (wr + r) * 256;
            *(float4*)(hp + j0)       = make_float4(h[0], h[1], h[2], h[3]);
            *(float4*)(hp + 128 + j0) = make_float4(h[4], h[5], h[6], h[7]);
        }
    }
    __syncthreads();   // everyone done with sBUF(W1) and writing sH

    // ================= Stage 2: h2 = relu(LN(h1 @ W2^T + b2)) =================
    #pragma unroll
    for (int r = 0; r < RW; ++r)
        #pragma unroll
        for (int p = 0; p < 4; ++p) acc[r][p] = 0ull;

    #pragma unroll 1
    for (int pass = 0; pass < 2; ++pass) {
        const int k0 = pass * 128;
        // load W2 half: sBUF[k*256 + j] = W2[j*256 + k0 + k]; thread streams row j=tid
        #pragma unroll
        for (int it = 0; it < 32; ++it) {
            float4 v = *(const float4*)(W2 + tid * 256 + k0 + 4 * it);
            sBUF[(4 * it + 0) * 256 + tid] = v.x;
            sBUF[(4 * it + 1) * 256 + tid] = v.y;
            sBUF[(4 * it + 2) * 256 + tid] = v.z;
            sBUF[(4 * it + 3) * 256 + tid] = v.w;
        }
        __syncthreads();

        for (int k = 0; k < 128; ++k) {
            const float* wrow = sBUF + (k << 8);
            ulonglong2 wa = *(const ulonglong2*)(wrow + j0);
            ulonglong2 wb = *(const ulonglong2*)(wrow + 128 + j0);
            #pragma unroll
            for (int r = 0; r < RW; ++r) {
                unsigned long long hd = dup2(sH[(wr + r) * 256 + k0 + k]);
                ffma2(acc[r][0], wa.x, hd);
                ffma2(acc[r][1], wa.y, hd);
                ffma2(acc[r][2], wb.x, hd);
                ffma2(acc[r][3], wb.y, hd);
            }
        }
        __syncthreads();   // free sBUF for next fill
    }

    // load W3T while sBUF is free: sBUF[k*64 + j] = W3[j*256 + k]
    {
        const int j  = tid & 63;
        const int ks = (tid >> 6) * 64;    // 64-wide k segment
        #pragma unroll
        for (int it = 0; it < 16; ++it) {
            float4 v = *(const float4*)(W3 + j * 256 + ks + 4 * it);
            sBUF[(ks + 4 * it + 0) * 64 + j] = v.x;
            sBUF[(ks + 4 * it + 1) * 64 + j] = v.y;
            sBUF[(ks + 4 * it + 2) * 64 + j] = v.z;
            sBUF[(ks + 4 * it + 3) * 64 + j] = v.w;
        }
    }

    // LN2 + ReLU -> overwrite sH (own rows only)
    {
        float bj[8], gj[8], bej[8];
        #pragma unroll
        for (int c = 0; c < 4; ++c) {
            bj[c]      = b2[j0 + c];        bj[4 + c]  = b2[128 + j0 + c];
            gj[c]      = g2[j0 + c];        gj[4 + c]  = g2[128 + j0 + c];
            bej[c]     = be2[j0 + c];       bej[4 + c] = be2[128 + j0 + c];
        }
        #pragma unroll
        for (int r = 0; r < RW; ++r) {
            float v[8]; float2 t;
            t = unpk(acc[r][0]); v[0] = t.x + bj[0]; v[1] = t.y + bj[1];
            t = unpk(acc[r][1]); v[2] = t.x + bj[2]; v[3] = t.y + bj[3];
            t = unpk(acc[r][2]); v[4] = t.x + bj[4]; v[5] = t.y + bj[5];
            t = unpk(acc[r][3]); v[6] = t.x + bj[6]; v[7] = t.y + bj[7];
            float s = 0.f, s2 = 0.f;
            #pragma unroll
            for (int c = 0; c < 8; ++c) { s += v[c]; s2 += v[c] * v[c]; }
            s = wredsum(s); s2 = wredsum(s2);
            float mean = s * (1.0f / 256.0f);
            float var  = s2 * (1.0f / 256.0f) - mean * mean;
            float rstd = rsqrtf(var + 1e-5f);
            float h[8];
            #pragma unroll
            for (int c = 0; c < 8; ++c)
                h[c] = fmaxf(0.f, (v[c] - mean) * rstd * gj[c] + bej[c]);
            float* hp = sH + (wr + r) * 256;
            *(float4*)(hp + j0)       = make_float4(h[0], h[1], h[2], h[3]);
            *(float4*)(hp + 128 + j0) = make_float4(h[4], h[5], h[6], h[7]);
        }
    }
    __syncthreads();   // W3T loaded + h2 visible

    // ================= Stage 3: logits = h2 @ W3^T + b3 =================
    unsigned long long a3[RW];
    #pragma unroll
    for (int r = 0; r < RW; ++r) a3[r] = 0ull;

    for (int k = 0; k < 256; ++k) {
        unsigned long long wp = *(const unsigned long long*)(sBUF + (k << 6) + 2 * l);
        #pragma unroll
        for (int r = 0; r < RW; ++r) {
            unsigned long long hd = dup2(sH[(wr + r) * 256 + k]);
            ffma2(a3[r], wp, hd);
        }
    }

    // ================= Softmax + causal shift-sum =================
    const float b3a = b3[2 * l];
    const float b3b = b3[2 * l + 1];
    #pragma unroll
    for (int r = 0; r < RW; ++r) {
        float2 t = unpk(a3[r]);
        float l0 = t.x + b3a, l1 = t.y + b3b;
        float m = wredmax(fmaxf(l0, l1));
        float e0 = expf(l0 - m), e1 = expf(l1 - m);
        float sum = wredsum(e0 + e1);
        float inv = 1.0f / sum;
        // store probs into sH row (h2 region no longer needed)
        *(float2*)(sH + (wr + r) * 256 + 2 * l) = make_float2(e0 * inv, e1 * inv);
    }
    __syncwarp();

    const int i0 = 2 * l, i1 = 2 * l + 1;
    #pragma unroll
    for (int r = 0; r < RW; ++r) {
        const float* pr = sH + (wr + r) * 256;
        const float* ar = sA + (wr + r) * 64;
        float o0 = 0.f, o1 = 0.f;
        for (int s = 0; s <= i1; ++s) {
            float pv = pr[s];
            if (s <= i0) o0 += pv * ar[i0 - s];
            o1 += pv * ar[i1 - s];
        }
        *(float2*)(out + (size_t)(r0 + wr + r) * 64 + i0) = make_float2(o0, o1);
    }
}

extern "C" void kernel_launch(void* const* d_in, const int* in_sizes, int n_in,
                              void* d_out, int out_size)
{
    const float* a_bits     = (const float*)d_in[0];
    const float* shift_bits = (const float*)d_in[1];
    const float* W1  = (const float*)d_in[2];
    const float* b1  = (const float*)d_in[3];
    const float* g1  = (const float*)d_in[4];
    const float* be1 = (const float*)d_in[5];
    const float* W2  = (const float*)d_in[6];
    const float* b2  = (const float*)d_in[7];
    const float* g2  = (const float*)d_in[8];
    const float* be2 = (const float*)d_in[9];
    const float* W3  = (const float*)d_in[10];
    const float* b3  = (const float*)d_in[11];
    float* out = (float*)d_out;

    const int B = in_sizes[0] / BITS;     // 32768
    const int grid = B / RB;              // 512

    static int smem_bytes = SMEM_FLOATS * (int)sizeof(float);   // 229376
    cudaFuncSetAttribute(shiftdec_fused,
                         cudaFuncAttributeMaxDynamicSharedMemorySize, smem_bytes);
    shiftdec_fused<<<grid, NT, smem_bytes>>>(a_bits, shift_bits,
                                             W1, b1, g1, be1,
                                             W2, b2, g2, be2,
                                             W3, b3, out);
}

// round 2
// speedup vs baseline: 1.0024x; 1.0024x over previous
#include <cuda_runtime.h>

// ShiftDecoderNet fused kernel: 3-layer MLP (LN+ReLU) + softmax + causal shift-sum.
// One CTA = 64 rows. 8 warps x 8 rows/warp. Each lane owns 8 output cols
// (j = 4*lane .. 4*lane+3 and 128+4*lane .. +3) x 8 rows of fp32 accumulators,
// packed as f32x2 for fma.rn.f32x2. Weights staged through a 128KB shared buffer.

#define BITS 64
#define HID 256
#define RB 64      // rows per block
#define NT 256     // threads per block
#define RW 8       // rows per warp

__device__ __forceinline__ void ffma2(unsigned long long &c, unsigned long long a, unsigned long long b) {
    asm("fma.rn.f32x2 %0, %1, %2, %0;" : "+l"(c) : "l"(a), "l"(b));
}
__device__ __forceinline__ unsigned long long dup2(float x) {
    unsigned long long d;
    asm("mov.b64 %0, {%1, %1};" : "=l"(d) : "f"(x));
    return d;
}
__device__ __forceinline__ float2 unpk(unsigned long long v) {
    float2 r;
    asm("mov.b64 {%0, %1}, %2;" : "=f"(r.x), "=f"(r.y) : "l"(v));
    return r;
}
__device__ __forceinline__ float wredsum(float v) {
    #pragma unroll
    for (int o = 16; o; o >>= 1) v += __shfl_xor_sync(0xffffffffu, v, o);
    return v;
}
__device__ __forceinline__ float wredmax(float v) {
    #pragma unroll
    for (int o = 16; o; o >>= 1) v = fmaxf(v, __shfl_xor_sync(0xffffffffu, v, o));
    return v;
}

// Shared layout (floats):
//   sBUF: [0, 32768)          128KB weight staging (W1T / W2 half / W3T)
//   sH:   [32768, 49152)      64 rows x 256 activations (h1, then h2, then probs)
//   sX:   [49152, 53248)      64 x 64 shift_bits
//   sA:   [53248, 57344)      64 x 64 a_bits
#define SMEM_FLOATS 57344

extern "C" __global__ void __launch_bounds__(NT, 1)
shiftdec_fused(const float* __restrict__ a_bits, const float* __restrict__ shift_bits,
               const float* __restrict__ W1, const float* __restrict__ b1,
               const float* __restrict__ g1, const float* __restrict__ be1,
               const float* __restrict__ W2, const float* __restrict__ b2,
               const float* __restrict__ g2, const float* __restrict__ be2,
               const float* __restrict__ W3, const float* __restrict__ b3,
               float* __restrict__ out)
{
    extern __shared__ float smem[];
    float* sBUF = smem;
    float* sH   = smem + 32768;
    float* sX   = smem + 49152;
    float* sA   = smem + 53248;

    const int tid = threadIdx.x;
    const int l   = tid & 31;
    const int w   = tid >> 5;
    const int wr  = w * RW;                 // local row base for this warp
    const int r0  = blockIdx.x * RB;        // global row base
    const int j0  = l * 4;

    // ---- cooperative loads: sX, sA (vectorized), W1T into sBUF ----
    {
        const float4* xs = (const float4*)(shift_bits + (size_t)r0 * BITS);
        const float4* as = (const float4*)(a_bits + (size_t)r0 * BITS);
        float4* dx = (float4*)sX;
        float4* da = (float4*)sA;
        #pragma unroll
        for (int it = 0; it < (RB * BITS / 4) / NT; ++it) {
            dx[tid + NT * it] = xs[tid + NT * it];
            da[tid + NT * it] = as[tid + NT * it];
        }
        // W1T: sBUF[k*256 + j] = W1[j*64 + k]; thread tid streams row j=tid.
        #pragma unroll
        for (int it = 0; it < 16; ++it) {
            float4 v = *(const float4*)(W1 + tid * 64 + 4 * it);
            sBUF[(4 * it + 0) * 256 + tid] = v.x;
            sBUF[(4 * it + 1) * 256 + tid] = v.y;
            sBUF[(4 * it + 2) * 256 + tid] = v.z;
            sBUF[(4 * it + 3) * 256 + tid] = v.w;
        }
    }
    __syncthreads();

    // ================= Stage 1: h1 = relu(LN(x @ W1^T + b1)) =================
    unsigned long long acc[RW][4];
    #pragma unroll
    for (int r = 0; r < RW; ++r)
        #pragma unroll
        for (int p = 0; p < 4; ++p) acc[r][p] = 0ull;

    for (int k = 0; k < 64; ++k) {
        const float* wrow = sBUF + (k << 8);
        ulonglong2 wa = *(const ulonglong2*)(wrow + j0);
        ulonglong2 wb = *(const ulonglong2*)(wrow + 128 + j0);
        #pragma unroll
        for (int r = 0; r < RW; ++r) {
            unsigned long long hd = dup2(sX[(wr + r) * 64 + k]);
            ffma2(acc[r][0], wa.x, hd);
            ffma2(acc[r][1], wa.y, hd);
            ffma2(acc[r][2], wb.x, hd);
            ffma2(acc[r][3], wb.y, hd);
        }
    }

    // LN1 + ReLU -> sH (own rows)
    {
        float bj[8], gj[8], bej[8];
        #pragma unroll
        for (int c = 0; c < 4; ++c) {
            bj[c]      = b1[j0 + c];        bj[4 + c]  = b1[128 + j0 + c];
            gj[c]      = g1[j0 + c];        gj[4 + c]  = g1[128 + j0 + c];
            bej[c]     = be1[j0 + c];       bej[4 + c] = be1[128 + j0 + c];
        }
        #pragma unroll
        for (int r = 0; r < RW; ++r) {
            float v[8]; float2 t;
            t = unpk(acc[r][0]); v[0] = t.x + bj[0]; v[1] = t.y + bj[1];
            t = unpk(acc[r][1]); v[2] = t.x + bj[2]; v[3] = t.y + bj[3];
            t = unpk(acc[r][2]); v[4] = t.x + bj[4]; v[5] = t.y + bj[5];
            t = unpk(acc[r][3]); v[6] = t.x + bj[6]; v[7] = t.y + bj[7];
            float s = 0.f, s2 = 0.f;
            #pragma unroll
            for (int c = 0; c < 8; ++c) { s += v[c]; s2 += v[c] * v[c]; }
            s = wredsum(s); s2 = wredsum(s2);
            float mean = s * (1.0f / 256.0f);
            float var  = s2 * (1.0f / 256.0f) - mean * mean;
            float rstd = rsqrtf(var + 1e-5f);
            float h[8];
            #pragma unroll
            for (int c = 0; c < 8; ++c)
                h[c] = fmaxf(0.f, (v[c] - mean) * rstd * gj[c] + bej[c]);
            float* hp = sH + (wr + r) * 256;
            *(float4*)(hp + j0)       = make_float4(h[0], h[1], h[2], h[3]);
            *(float4*)(hp + 128 + j0) = make_float4(h[4], h[5], h[6], h[7]);
        }
    }
    __syncthreads();   // everyone done with sBUF(W1) and writing sH

    // ================= Stage 2: h2 = relu(LN(h1 @ W2^T + b2)) =================
    #pragma unroll
    for (int r = 0; r < RW; ++r)
        #pragma unroll
        for (int p = 0; p < 4; ++p) acc[r][p] = 0ull;

    #pragma unroll 1
    for (int pass = 0; pass < 2; ++pass) {
        const int k0 = pass * 128;
        // load W2 half: sBUF[k*256 + j] = W2[j*256 + k0 + k]; thread streams row j=tid
        #pragma unroll
        for (int it = 0; it < 32; ++it) {
            float4 v = *(const float4*)(W2 + tid * 256 + k0 + 4 * it);
            sBUF[(4 * it + 0) * 256 + tid] = v.x;
            sBUF[(4 * it + 1) * 256 + tid] = v.y;
            sBUF[(4 * it + 2) * 256 + tid] = v.z;
            sBUF[(4 * it + 3) * 256 + tid] = v.w;
        }
        __syncthreads();

        for (int k = 0; k < 128; ++k) {
            const float* wrow = sBUF + (k << 8);
            ulonglong2 wa = *(const ulonglong2*)(wrow + j0);
            ulonglong2 wb = *(const ulonglong2*)(wrow + 128 + j0);
            #pragma unroll
            for (int r = 0; r < RW; ++r) {
                unsigned long long hd = dup2(sH[(wr + r) * 256 + k0 + k]);
                ffma2(acc[r][0], wa.x, hd);
                ffma2(acc[r][1], wa.y, hd);
                ffma2(acc[r][2], wb.x, hd);
                ffma2(acc[r][3], wb.y, hd);
            }
        }
        __syncthreads();   // free sBUF for next fill
    }

    // load W3T while sBUF is free: sBUF[k*64 + j] = W3[j*256 + k]
    {
        const int j  = tid & 63;
        const int ks = (tid >> 6) * 64;    // 64-wide k segment
        #pragma unroll
        for (int it = 0; it < 16; ++it) {
            float4 v = *(const float4*)(W3 + j * 256 + ks + 4 * it);
            sBUF[(ks + 4 * it + 0) * 64 + j] = v.x;
            sBUF[(ks + 4 * it + 1) * 64 + j] = v.y;
            sBUF[(ks + 4 * it + 2) * 64 + j] = v.z;
            sBUF[(ks + 4 * it + 3) * 64 + j] = v.w;
        }
    }

    // LN2 + ReLU -> overwrite sH (own rows only)
    {
        float bj[8], gj[8], bej[8];
        #pragma unroll
        for (int c = 0; c < 4; ++c) {
            bj[c]      = b2[j0 + c];        bj[4 + c]  = b2[128 + j0 + c];
            gj[c]      = g2[j0 + c];        gj[4 + c]  = g2[128 + j0 + c];
            bej[c]     = be2[j0 + c];       bej[4 + c] = be2[128 + j0 + c];
        }
        #pragma unroll
        for (int r = 0; r < RW; ++r) {
            float v[8]; float2 t;
            t = unpk(acc[r][0]); v[0] = t.x + bj[0]; v[1] = t.y + bj[1];
            t = unpk(acc[r][1]); v[2] = t.x + bj[2]; v[3] = t.y + bj[3];
            t = unpk(acc[r][2]); v[4] = t.x + bj[4]; v[5] = t.y + bj[5];
            t = unpk(acc[r][3]); v[6] = t.x + bj[6]; v[7] = t.y + bj[7];
            float s = 0.f, s2 = 0.f;
            #pragma unroll
            for (int c = 0; c < 8; ++c) { s += v[c]; s2 += v[c] * v[c]; }
            s = wredsum(s); s2 = wredsum(s2);
            float mean = s * (1.0f / 256.0f);
            float var  = s2 * (1.0f / 256.0f) - mean * mean;
            float rstd = rsqrtf(var + 1e-5f);
            float h[8];
            #pragma unroll
            for (int c = 0; c < 8; ++c)
                h[c] = fmaxf(0.f, (v[c] - mean) * rstd * gj[c] + bej[c]);
            float* hp = sH + (wr + r) * 256;
            *(float4*)(hp + j0)       = make_float4(h[0], h[1], h[2], h[3]);
            *(float4*)(hp + 128 + j0) = make_float4(h[4], h[5], h[6], h[7]);
        }
    }
    __syncthreads();   // W3T loaded + h2 visible

    // ================= Stage 3: logits = h2 @ W3^T + b3 =================
    unsigned long long a3[RW];
    #pragma unroll
    for (int r = 0; r < RW; ++r) a3[r] = 0ull;

    for (int k = 0; k < 256; ++k) {
        unsigned long long wp = *(const unsigned long long*)(sBUF + (k << 6) + 2 * l);
        #pragma unroll
        for (int r = 0; r < RW; ++r) {
            unsigned long long hd = dup2(sH[(wr + r) * 256 + k]);
            ffma2(a3[r], wp, hd);
        }
    }

    // ================= Softmax + causal shift-sum =================
    const float b3a = b3[2 * l];
    const float b3b = b3[2 * l + 1];
    #pragma unroll
    for (int r = 0; r < RW; ++r) {
        float2 t = unpk(a3[r]);
        float l0 = t.x + b3a, l1 = t.y + b3b;
        float m = wredmax(fmaxf(l0, l1));
        float e0 = expf(l0 - m), e1 = expf(l1 - m);
        float sum = wredsum(e0 + e1);
        float inv = 1.0f / sum;
        // store probs into sH row (h2 region no longer needed)
        *(float2*)(sH + (wr + r) * 256 + 2 * l) = make_float2(e0 * inv, e1 * inv);
    }
    __syncwarp();

    const int i0 = 2 * l, i1 = 2 * l + 1;
    #pragma unroll
    for (int r = 0; r < RW; ++r) {
        const float* pr = sH + (wr + r) * 256;
        const float* ar = sA + (wr + r) * 64;
        float o0 = 0.f, o1 = 0.f;
        for (int s = 0; s <= i1; ++s) {
            float pv = pr[s];
            if (s <= i0) o0 += pv * ar[i0 - s];
            o1 += pv * ar[i1 - s];
        }
        *(float2*)(out + (size_t)(r0 + wr + r) * 64 + i0) = make_float2(o0, o1);
    }
}

extern "C" void kernel_launch(void* const* d_in, const int* in_sizes, int n_in,
                              void* d_out, int out_size)
{
    const float* a_bits     = (const float*)d_in[0];
    const float* shift_bits = (const float*)d_in[1];
    const float* W1  = (const float*)d_in[2];
    const float* b1  = (const float*)d_in[3];
    const float* g1  = (const float*)d_in[4];
    const float* be1 = (const float*)d_in[5];
    const float* W2  = (const float*)d_in[6];
    const float* b2  = (const float*)d_in[7];
    const float* g2  = (const float*)d_in[8];
    const float* be2 = (const float*)d_in[9];
    const float* W3  = (const float*)d_in[10];
    const float* b3  = (const float*)d_in[11];
    float* out = (float*)d_out;

    const int B = in_sizes[0] / BITS;     // 32768
    const int grid = B / RB;              // 512

    static int smem_bytes = SMEM_FLOATS * (int)sizeof(float);   // 229376
    cudaFuncSetAttribute(shiftdec_fused,
                         cudaFuncAttributeMaxDynamicSharedMemorySize, smem_bytes);
    shiftdec_fused<<<grid, NT, smem_bytes>>>(a_bits, shift_bits,
                                             W1, b1, g1, be1,
                                             W2, b2, g2, be2,
                                             W3, b3, out);
}